// round 1
// baseline (speedup 1.0000x reference)
#include <cuda_runtime.h>
#include <cuda_bf16.h>

// ---------------------------------------------------------------------------
// PubMedGAT: 2-layer GAT
//   L1: f1 = X@W1 -> [N,4,64]; attention softmax over incoming edges; agg; ELU
//   L2: f2 = h1@W2 -> [N,1,64]; attention softmax; agg; +bias
// ---------------------------------------------------------------------------

#define N_NODES 50000
#define N_EDGES 800000
#define IN_DIM  512
#define HEADS   4
#define HID     64
#define F1DIM   (HEADS*HID)   // 256
#define OUTD    64
#define NEG_SLOPE 0.2f
#define NEG_INF_ENC 0x007FFFFFu   // ordered-uint encoding of -inf

// ------------------------- scratch (device globals) -------------------------
__device__ float    g_f1  [N_NODES * F1DIM];
__device__ float    g_agg1[N_NODES * F1DIM];   // becomes h1 after ELU
__device__ float    g_el1 [N_NODES * HEADS];
__device__ float    g_er1 [N_NODES * HEADS];
__device__ unsigned g_m1  [N_NODES * HEADS];
__device__ float    g_den1[N_NODES * HEADS];
__device__ float    g_e1  [N_EDGES * HEADS];   // e, then overwritten with exp(e-m)
__device__ float    g_f2  [N_NODES * OUTD];
__device__ float    g_el2 [N_NODES];
__device__ float    g_er2 [N_NODES];
__device__ unsigned g_m2  [N_NODES];
__device__ float    g_den2[N_NODES];
__device__ float    g_e2  [N_EDGES];

// ------------------------------ helpers -------------------------------------
__device__ __forceinline__ unsigned enc_f(float f) {
    unsigned u = __float_as_uint(f);
    return (u & 0x80000000u) ? ~u : (u | 0x80000000u);
}
__device__ __forceinline__ float dec_f(unsigned u) {
    return (u & 0x80000000u) ? __uint_as_float(u ^ 0x80000000u)
                             : __uint_as_float(~u);
}
__device__ __forceinline__ float lrelu(float x) {
    return x >= 0.0f ? x : NEG_SLOPE * x;
}
__device__ __forceinline__ void red_add_v4(float* p, float4 v) {
    asm volatile("red.global.add.v4.f32 [%0], {%1, %2, %3, %4};"
                 :: "l"(p), "f"(v.x), "f"(v.y), "f"(v.z), "f"(v.w) : "memory");
}

// ------------------------------ init ----------------------------------------
__global__ void init_kernel(float* out) {
    int i = blockIdx.x * blockDim.x + threadIdx.x;
    int stride = gridDim.x * blockDim.x;
    for (int j = i; j < N_NODES * F1DIM; j += stride) g_agg1[j] = 0.0f;
    for (int j = i; j < N_NODES * OUTD;  j += stride) out[j]    = 0.0f;
    for (int j = i; j < N_NODES * HEADS; j += stride) { g_den1[j] = 0.0f; g_m1[j] = NEG_INF_ENC; }
    for (int j = i; j < N_NODES;         j += stride) { g_den2[j] = 0.0f; g_m2[j] = NEG_INF_ENC; }
}

// ------------------------------ SGEMM ----------------------------------------
// C[M,N] = A[M,K] @ B[K,N], row-major. BM=BN=64, BK=16, 256 threads, 4x4 micro.
// Requires N%64==0, K%16==0. Rows of A/C guarded against M.
__global__ void sgemm_kernel(const float* __restrict__ A,
                             const float* __restrict__ B,
                             float* __restrict__ C,
                             int M, int N, int K) {
    __shared__ float As[16][64];
    __shared__ float Bs[16][64];
    const int tid = threadIdx.x;
    const int bm = blockIdx.y * 64;
    const int bn = blockIdx.x * 64;
    const int tx = tid & 15;    // 0..15 -> 4 cols each
    const int ty = tid >> 4;    // 0..15 -> 4 rows each

    float acc[4][4];
#pragma unroll
    for (int i = 0; i < 4; i++)
#pragma unroll
        for (int j = 0; j < 4; j++) acc[i][j] = 0.0f;

    const int am = tid >> 2;          // 0..63
    const int ac = (tid & 3) * 4;     // 0,4,8,12
    const int bk = tid >> 4;          // 0..15
    const int bn0 = (tid & 15) * 4;   // 0..60

    for (int k0 = 0; k0 < K; k0 += 16) {
        float4 av = make_float4(0.f, 0.f, 0.f, 0.f);
        if (bm + am < M)
            av = *(const float4*)&A[(size_t)(bm + am) * K + k0 + ac];
        As[ac + 0][am] = av.x;
        As[ac + 1][am] = av.y;
        As[ac + 2][am] = av.z;
        As[ac + 3][am] = av.w;
        float4 bv = *(const float4*)&B[(size_t)(k0 + bk) * N + bn + bn0];
        *(float4*)&Bs[bk][bn0] = bv;
        __syncthreads();
#pragma unroll
        for (int kk = 0; kk < 16; kk++) {
            float ar[4], br[4];
#pragma unroll
            for (int i = 0; i < 4; i++) ar[i] = As[kk][ty * 4 + i];
#pragma unroll
            for (int j = 0; j < 4; j++) br[j] = Bs[kk][tx * 4 + j];
#pragma unroll
            for (int i = 0; i < 4; i++)
#pragma unroll
                for (int j = 0; j < 4; j++) acc[i][j] += ar[i] * br[j];
        }
        __syncthreads();
    }
#pragma unroll
    for (int i = 0; i < 4; i++) {
        int row = bm + ty * 4 + i;
        if (row < M) {
            float4 v = make_float4(acc[i][0], acc[i][1], acc[i][2], acc[i][3]);
            *(float4*)&C[(size_t)row * N + bn + tx * 4] = v;
        }
    }
}

// --------------------- el/er projections (warp per node-head) ----------------
__global__ void elr1_kernel(const float* __restrict__ al,
                            const float* __restrict__ ar) {
    int w = (blockIdx.x * blockDim.x + threadIdx.x) >> 5;
    int lane = threadIdx.x & 31;
    if (w >= N_NODES * HEADS) return;
    int n = w >> 2, h = w & 3;
    const float* frow = g_f1 + (size_t)n * F1DIM + h * HID;
    float sl = 0.f, sr = 0.f;
#pragma unroll
    for (int i = lane; i < HID; i += 32) {
        float f = frow[i];
        sl += f * al[h * HID + i];
        sr += f * ar[h * HID + i];
    }
#pragma unroll
    for (int o = 16; o > 0; o >>= 1) {
        sl += __shfl_xor_sync(0xFFFFFFFFu, sl, o);
        sr += __shfl_xor_sync(0xFFFFFFFFu, sr, o);
    }
    if (lane == 0) { g_el1[n * 4 + h] = sl; g_er1[n * 4 + h] = sr; }
}

__global__ void elr2_kernel(const float* __restrict__ al,
                            const float* __restrict__ ar) {
    int w = (blockIdx.x * blockDim.x + threadIdx.x) >> 5;
    int lane = threadIdx.x & 31;
    if (w >= N_NODES) return;
    const float* frow = g_f2 + (size_t)w * OUTD;
    float sl = 0.f, sr = 0.f;
#pragma unroll
    for (int i = lane; i < OUTD; i += 32) {
        float f = frow[i];
        sl += f * al[i];
        sr += f * ar[i];
    }
#pragma unroll
    for (int o = 16; o > 0; o >>= 1) {
        sl += __shfl_xor_sync(0xFFFFFFFFu, sl, o);
        sr += __shfl_xor_sync(0xFFFFFFFFu, sr, o);
    }
    if (lane == 0) { g_el2[w] = sl; g_er2[w] = sr; }
}

// --------------------------- edge pass A: e + segmax -------------------------
__global__ void edgeA1_kernel(const int* __restrict__ src,
                              const int* __restrict__ dst) {
    int e = blockIdx.x * blockDim.x + threadIdx.x;
    if (e >= N_EDGES) return;
    int s = src[e], d = dst[e];
    float4 el = *(const float4*)&g_el1[s * 4];
    float4 er = *(const float4*)&g_er1[d * 4];
    float4 ev;
    ev.x = lrelu(el.x + er.x);
    ev.y = lrelu(el.y + er.y);
    ev.z = lrelu(el.z + er.z);
    ev.w = lrelu(el.w + er.w);
    *(float4*)&g_e1[e * 4] = ev;
    atomicMax(&g_m1[d * 4 + 0], enc_f(ev.x));
    atomicMax(&g_m1[d * 4 + 1], enc_f(ev.y));
    atomicMax(&g_m1[d * 4 + 2], enc_f(ev.z));
    atomicMax(&g_m1[d * 4 + 3], enc_f(ev.w));
}

__global__ void edgeA2_kernel(const int* __restrict__ src,
                              const int* __restrict__ dst) {
    int e = blockIdx.x * blockDim.x + threadIdx.x;
    if (e >= N_EDGES) return;
    int s = src[e], d = dst[e];
    float ev = lrelu(g_el2[s] + g_er2[d]);
    g_e2[e] = ev;
    atomicMax(&g_m2[d], enc_f(ev));
}

// ------------------------ edge pass B: exp + densum --------------------------
__global__ void edgeB1_kernel(const int* __restrict__ dst) {
    int e = blockIdx.x * blockDim.x + threadIdx.x;
    if (e >= N_EDGES) return;
    int d = dst[e];
    float4 ev = *(const float4*)&g_e1[e * 4];
    uint4 mu = *(const uint4*)&g_m1[d * 4];
    float4 ex;
    ex.x = expf(ev.x - dec_f(mu.x));
    ex.y = expf(ev.y - dec_f(mu.y));
    ex.z = expf(ev.z - dec_f(mu.z));
    ex.w = expf(ev.w - dec_f(mu.w));
    *(float4*)&g_e1[e * 4] = ex;
    atomicAdd(&g_den1[d * 4 + 0], ex.x);
    atomicAdd(&g_den1[d * 4 + 1], ex.y);
    atomicAdd(&g_den1[d * 4 + 2], ex.z);
    atomicAdd(&g_den1[d * 4 + 3], ex.w);
}

__global__ void edgeB2_kernel(const int* __restrict__ dst) {
    int e = blockIdx.x * blockDim.x + threadIdx.x;
    if (e >= N_EDGES) return;
    int d = dst[e];
    float ex = expf(g_e2[e] - dec_f(g_m2[d]));
    g_e2[e] = ex;
    atomicAdd(&g_den2[d], ex);
}

// -------------------- edge pass C: weighted scatter-agg ----------------------
// L1: 64 threads per edge (each does one float4 of the 256-wide feature row).
__global__ void edgeC1_kernel(const int* __restrict__ src,
                              const int* __restrict__ dst) {
    long long t = (long long)blockIdx.x * blockDim.x + threadIdx.x;
    int e = (int)(t >> 6);
    int lane = (int)(t & 63);
    if (e >= N_EDGES) return;
    int s = src[e], d = dst[e];
    int h = lane >> 4;  // 16 float4s per head
    float a = g_e1[e * 4 + h] / g_den1[d * 4 + h];
    float4 f = *(const float4*)&g_f1[(size_t)s * F1DIM + lane * 4];
    red_add_v4(&g_agg1[(size_t)d * F1DIM + lane * 4],
               make_float4(a * f.x, a * f.y, a * f.z, a * f.w));
}

// L2: 16 threads per edge (64-wide feature row).
__global__ void edgeC2_kernel(const int* __restrict__ src,
                              const int* __restrict__ dst,
                              float* __restrict__ out) {
    long long t = (long long)blockIdx.x * blockDim.x + threadIdx.x;
    int e = (int)(t >> 4);
    int lane = (int)(t & 15);
    if (e >= N_EDGES) return;
    int s = src[e], d = dst[e];
    float a = g_e2[e] / g_den2[d];
    float4 f = *(const float4*)&g_f2[(size_t)s * OUTD + lane * 4];
    red_add_v4(&out[(size_t)d * OUTD + lane * 4],
               make_float4(a * f.x, a * f.y, a * f.z, a * f.w));
}

// --------------------- bias + ELU (in-place on agg1 -> h1) -------------------
__global__ void elu_bias_kernel(const float* __restrict__ b1) {
    int i = blockIdx.x * blockDim.x + threadIdx.x;
    if (i >= N_NODES * F1DIM) return;
    float v = g_agg1[i] + b1[i & (F1DIM - 1)];
    g_agg1[i] = v > 0.0f ? v : expm1f(v);
}

__global__ void bias2_kernel(float* __restrict__ out,
                             const float* __restrict__ b2) {
    int i = blockIdx.x * blockDim.x + threadIdx.x;
    if (i >= N_NODES * OUTD) return;
    out[i] = out[i] + b2[i & (OUTD - 1)];
}

// ------------------------------ launch --------------------------------------
extern "C" void kernel_launch(void* const* d_in, const int* in_sizes, int n_in,
                              void* d_out, int out_size) {
    const float* features = (const float*)d_in[0];
    const float* W1  = (const float*)d_in[1];
    const float* al1 = (const float*)d_in[2];
    const float* ar1 = (const float*)d_in[3];
    const float* b1  = (const float*)d_in[4];
    const float* W2  = (const float*)d_in[5];
    const float* al2 = (const float*)d_in[6];
    const float* ar2 = (const float*)d_in[7];
    const float* b2  = (const float*)d_in[8];
    const int*   src = (const int*)d_in[9];
    const int*   dst = (const int*)d_in[10];
    float* out = (float*)d_out;

    // fetch scratch symbol addresses (query only; not a stream op)
    float *p_f1, *p_agg1, *p_f2;
    cudaGetSymbolAddress((void**)&p_f1, g_f1);
    cudaGetSymbolAddress((void**)&p_agg1, g_agg1);
    cudaGetSymbolAddress((void**)&p_f2, g_f2);

    // 0. init scratch
    init_kernel<<<4096, 256>>>(out);

    // 1. GEMM1: f1 = X @ W1   [50000,512]x[512,256]
    {
        dim3 grid(F1DIM / 64, (N_NODES + 63) / 64);
        sgemm_kernel<<<grid, 256>>>(features, W1, p_f1, N_NODES, F1DIM, IN_DIM);
    }

    // 2. el1/er1
    elr1_kernel<<<(N_NODES * HEADS * 32 + 255) / 256, 256>>>(al1, ar1);

    // 3-5. edge passes layer 1
    edgeA1_kernel<<<(N_EDGES + 255) / 256, 256>>>(src, dst);
    edgeB1_kernel<<<(N_EDGES + 255) / 256, 256>>>(dst);
    edgeC1_kernel<<<(int)(((long long)N_EDGES * 64 + 255) / 256), 256>>>(src, dst);

    // 6. h1 = elu(agg1 + b1) in place
    elu_bias_kernel<<<(N_NODES * F1DIM + 255) / 256, 256>>>(b1);

    // 7. GEMM2: f2 = h1 @ W2   [50000,256]x[256,64]
    {
        dim3 grid(OUTD / 64, (N_NODES + 63) / 64);
        sgemm_kernel<<<grid, 256>>>(p_agg1, W2, p_f2, N_NODES, OUTD, F1DIM);
    }

    // 8. el2/er2
    elr2_kernel<<<(N_NODES * 32 + 255) / 256, 256>>>(al2, ar2);

    // 9-11. edge passes layer 2 (aggregate straight into d_out)
    edgeA2_kernel<<<(N_EDGES + 255) / 256, 256>>>(src, dst);
    edgeB2_kernel<<<(N_EDGES + 255) / 256, 256>>>(dst);
    edgeC2_kernel<<<(int)(((long long)N_EDGES * 16 + 255) / 256), 256>>>(src, dst, out);

    // 12. + b2
    bias2_kernel<<<(N_NODES * OUTD + 255) / 256, 256>>>(out, b2);
}

// round 3
// speedup vs baseline: 1.3860x; 1.3860x over previous
#include <cuda_runtime.h>
#include <cuda_bf16.h>
#include <math.h>

// ---------------------------------------------------------------------------
// PubMedGAT, round 2:
//  - FFMA2 (fp32x2 packed) SGEMM for both GEMMs
//  - CSR-by-dst edge phase: one warp per destination node does
//    online softmax + weighted gather, no global atomics on features
// ---------------------------------------------------------------------------

#define N_NODES 50000
#define N_EDGES 800000
#define IN_DIM  512
#define HEADS   4
#define HID     64
#define F1DIM   (HEADS*HID)   // 256
#define OUTD    64
#define NEG_SLOPE 0.2f

// ------------------------- scratch (device globals) -------------------------
__device__ float g_f1 [N_NODES * F1DIM];
__device__ float g_h1 [N_NODES * F1DIM];
__device__ float g_f2 [N_NODES * OUTD];
__device__ float g_el1[N_NODES * HEADS];
__device__ float g_er1[N_NODES * HEADS];
__device__ float g_el2[N_NODES];
__device__ float g_er2[N_NODES];
__device__ int   g_cnt[N_NODES + 1];     // counts -> CSR offsets
__device__ int   g_cursor[N_NODES];
__device__ int   g_csr_src[N_EDGES];

// ------------------------------ helpers -------------------------------------
__device__ __forceinline__ float lrelu(float x) {
    return x >= 0.0f ? x : NEG_SLOPE * x;
}

#define FFMA2(d, a, b) \
    asm("fma.rn.f32x2 %0, %1, %2, %0;" : "+l"(d) : "l"(a), "l"(b))

__device__ __forceinline__ unsigned long long dup_f32x2(float x) {
    unsigned long long r;
    unsigned u = __float_as_uint(x);
    asm("mov.b64 %0, {%1, %1};" : "=l"(r) : "r"(u));
    return r;
}
__device__ __forceinline__ float lo_f(unsigned long long v) {
    return __uint_as_float((unsigned)v);
}
__device__ __forceinline__ float hi_f(unsigned long long v) {
    return __uint_as_float((unsigned)(v >> 32));
}

// online softmax update: (m, q) <- merge with value e (e finite)
__device__ __forceinline__ void onl_upd(float& m, float& q, float e) {
    float nm = fmaxf(m, e);
    q = (m >= nm ? q : q * expf(m - nm)) + expf(e - nm);
    m = nm;
}
// combine two (m,q) pairs across lanes (NaN-safe when both are (-inf, 0))
__device__ __forceinline__ void onl_comb(float& m, float& q, int off) {
    float mo = __shfl_xor_sync(0xFFFFFFFFu, m, off);
    float qo = __shfl_xor_sync(0xFFFFFFFFu, q, off);
    float nm = fmaxf(m, mo);
    float t1 = (m  >= nm) ? q  : q  * expf(m  - nm);
    float t2 = (mo >= nm) ? qo : qo * expf(mo - nm);
    m = nm; q = t1 + t2;
}

// ------------------------------ CSR build -----------------------------------
__global__ void init_kernel() {
    int i = blockIdx.x * blockDim.x + threadIdx.x;
    if (i <= N_NODES) g_cnt[i] = 0;
}

__global__ void hist_kernel(const int* __restrict__ dst) {
    int e = blockIdx.x * blockDim.x + threadIdx.x;
    if (e < N_EDGES) atomicAdd(&g_cnt[dst[e]], 1);
}

// single-block exclusive scan over 50001 counters; also fills cursor
__global__ void scan_kernel() {
    __shared__ int sm[1024];
    const int t = threadIdx.x;
    const int CH = (N_NODES + 1023) / 1024;
    int lo = t * CH;
    int hi = min(N_NODES, lo + CH);
    int s = 0;
    for (int j = lo; j < hi; j++) s += g_cnt[j];
    sm[t] = s;
    __syncthreads();
    for (int off = 1; off < 1024; off <<= 1) {
        int u = (t >= off) ? sm[t - off] : 0;
        __syncthreads();
        if (t >= off) sm[t] += u;
        __syncthreads();
    }
    int run = (t > 0) ? sm[t - 1] : 0;
    for (int j = lo; j < hi; j++) {
        int c = g_cnt[j];
        g_cnt[j] = run;
        g_cursor[j] = run;
        run += c;
    }
    if (t == 1023) g_cnt[N_NODES] = run;
}

__global__ void fill_kernel(const int* __restrict__ src,
                            const int* __restrict__ dst) {
    int e = blockIdx.x * blockDim.x + threadIdx.x;
    if (e >= N_EDGES) return;
    int d = dst[e];
    int pos = atomicAdd(&g_cursor[d], 1);
    g_csr_src[pos] = src[e];
}

// ------------------------------ FFMA2 SGEMM ----------------------------------
// C[M,N] = A[M,K] @ B[K,N], row-major. BM=128, BN=64, BK=16, 256 threads.
// Thread microtile 8x4, accumulated as f32x2 pairs over adjacent rows.
// Requires N%64==0, K%16==0; row-guarded against M.
__global__ void sgemm_kernel(const float* __restrict__ A,
                             const float* __restrict__ B,
                             float* __restrict__ C,
                             int M, int N, int K) {
    __shared__ float As[16][128];
    __shared__ float Bs[16][64];
    const int tid = threadIdx.x;
    const int bm = blockIdx.y * 128;
    const int bn = blockIdx.x * 64;
    const int tx = tid & 15;          // col group: cols tx*4 .. +3
    const int ty = tid >> 4;          // row group: rows ty*8 .. +7

    const int ar = tid >> 1;          // 0..127  A-load row
    const int ac = (tid & 1) * 8;     // 0 or 8  A-load col base
    const int br = tid >> 4;          // 0..15   B-load row
    const int bc = (tid & 15) * 4;    // 0..60   B-load col base

    unsigned long long acc2[4][4];    // [row-pair][col]
#pragma unroll
    for (int i = 0; i < 4; i++)
#pragma unroll
        for (int j = 0; j < 4; j++) acc2[i][j] = 0ULL;

    const bool arow_ok = (bm + ar) < M;

    for (int k0 = 0; k0 < K; k0 += 16) {
        float4 a0 = make_float4(0.f, 0.f, 0.f, 0.f);
        float4 a1 = make_float4(0.f, 0.f, 0.f, 0.f);
        if (arow_ok) {
            const float* ap = &A[(size_t)(bm + ar) * K + k0 + ac];
            a0 = *(const float4*)(ap);
            a1 = *(const float4*)(ap + 4);
        }
        As[ac + 0][ar] = a0.x; As[ac + 1][ar] = a0.y;
        As[ac + 2][ar] = a0.z; As[ac + 3][ar] = a0.w;
        As[ac + 4][ar] = a1.x; As[ac + 5][ar] = a1.y;
        As[ac + 6][ar] = a1.z; As[ac + 7][ar] = a1.w;
        *(float4*)&Bs[br][bc] = *(const float4*)&B[(size_t)(k0 + br) * N + bn + bc];
        __syncthreads();
#pragma unroll
        for (int kk = 0; kk < 16; kk++) {
            unsigned long long av[4];
#pragma unroll
            for (int ip = 0; ip < 4; ip++)
                av[ip] = *(const unsigned long long*)&As[kk][ty * 8 + ip * 2];
            float4 b = *(const float4*)&Bs[kk][tx * 4];
            unsigned long long bd[4];
            bd[0] = dup_f32x2(b.x); bd[1] = dup_f32x2(b.y);
            bd[2] = dup_f32x2(b.z); bd[3] = dup_f32x2(b.w);
#pragma unroll
            for (int ip = 0; ip < 4; ip++)
#pragma unroll
                for (int j = 0; j < 4; j++)
                    FFMA2(acc2[ip][j], av[ip], bd[j]);
        }
        __syncthreads();
    }

#pragma unroll
    for (int ip = 0; ip < 4; ip++) {
        int r0 = bm + ty * 8 + ip * 2;
        if (r0 < M) {
            float4 v = make_float4(lo_f(acc2[ip][0]), lo_f(acc2[ip][1]),
                                   lo_f(acc2[ip][2]), lo_f(acc2[ip][3]));
            *(float4*)&C[(size_t)r0 * N + bn + tx * 4] = v;
        }
        if (r0 + 1 < M) {
            float4 v = make_float4(hi_f(acc2[ip][0]), hi_f(acc2[ip][1]),
                                   hi_f(acc2[ip][2]), hi_f(acc2[ip][3]));
            *(float4*)&C[(size_t)(r0 + 1) * N + bn + tx * 4] = v;
        }
    }
}

// --------------------- el/er projections (warp per node-head) ----------------
__global__ void elr1_kernel(const float* __restrict__ al,
                            const float* __restrict__ ar) {
    int w = (blockIdx.x * blockDim.x + threadIdx.x) >> 5;
    int lane = threadIdx.x & 31;
    if (w >= N_NODES * HEADS) return;
    int n = w >> 2, h = w & 3;
    const float* frow = g_f1 + (size_t)n * F1DIM + h * HID;
    float sl = 0.f, sr = 0.f;
#pragma unroll
    for (int i = lane; i < HID; i += 32) {
        float f = frow[i];
        sl += f * al[h * HID + i];
        sr += f * ar[h * HID + i];
    }
#pragma unroll
    for (int o = 16; o > 0; o >>= 1) {
        sl += __shfl_xor_sync(0xFFFFFFFFu, sl, o);
        sr += __shfl_xor_sync(0xFFFFFFFFu, sr, o);
    }
    if (lane == 0) { g_el1[n * 4 + h] = sl; g_er1[n * 4 + h] = sr; }
}

__global__ void elr2_kernel(const float* __restrict__ al,
                            const float* __restrict__ ar) {
    int w = (blockIdx.x * blockDim.x + threadIdx.x) >> 5;
    int lane = threadIdx.x & 31;
    if (w >= N_NODES) return;
    const float* frow = g_f2 + (size_t)w * OUTD;
    float sl = 0.f, sr = 0.f;
#pragma unroll
    for (int i = lane; i < OUTD; i += 32) {
        float f = frow[i];
        sl += f * al[i];
        sr += f * ar[i];
    }
#pragma unroll
    for (int o = 16; o > 0; o >>= 1) {
        sl += __shfl_xor_sync(0xFFFFFFFFu, sl, o);
        sr += __shfl_xor_sync(0xFFFFFFFFu, sr, o);
    }
    if (lane == 0) { g_el2[w] = sl; g_er2[w] = sr; }
}

// --------------- layer-1 aggregation: warp per dst, 4 heads ------------------
// Softmax over incoming edges (online), then weighted gather of f1[src].
// Writes h1 = elu(agg + b1) directly.
__global__ void agg1_kernel(const float* __restrict__ b1) {
    __shared__ float sm_a[8][128];   // per warp: 32 edges x 4 heads
    __shared__ int   sm_s[8][32];
    const int wid = threadIdx.x >> 5;
    const int lane = threadIdx.x & 31;
    const int d = blockIdx.x * 8 + wid;
    if (d >= N_NODES) return;
    const int start = g_cnt[d];
    const int end   = g_cnt[d + 1];

    float4 er = *(const float4*)&g_er1[d * 4];

    // pass 1: per-lane online softmax stats per head
    float m0 = -INFINITY, m1 = -INFINITY, m2 = -INFINITY, m3 = -INFINITY;
    float q0 = 0.f, q1 = 0.f, q2 = 0.f, q3 = 0.f;
    for (int base = start; base < end; base += 32) {
        int ei = base + lane;
        if (ei < end) {
            int s = g_csr_src[ei];
            float4 el = *(const float4*)&g_el1[s * 4];
            onl_upd(m0, q0, lrelu(el.x + er.x));
            onl_upd(m1, q1, lrelu(el.y + er.y));
            onl_upd(m2, q2, lrelu(el.z + er.z));
            onl_upd(m3, q3, lrelu(el.w + er.w));
        }
    }
#pragma unroll
    for (int off = 16; off > 0; off >>= 1) {
        onl_comb(m0, q0, off);
        onl_comb(m1, q1, off);
        onl_comb(m2, q2, off);
        onl_comb(m3, q3, off);
    }
    float i0 = q0 > 0.f ? 1.0f / q0 : 0.f;
    float i1 = q1 > 0.f ? 1.0f / q1 : 0.f;
    float i2 = q2 > 0.f ? 1.0f / q2 : 0.f;
    float i3 = q3 > 0.f ? 1.0f / q3 : 0.f;

    // pass 2: attention weights to smem, then feature gather
    const int hh = lane >> 3;           // head this lane aggregates
    float acc0 = 0.f, acc1 = 0.f, acc2 = 0.f, acc3 = 0.f;
    float acc4 = 0.f, acc5 = 0.f, acc6 = 0.f, acc7 = 0.f;
    for (int base = start; base < end; base += 32) {
        int ei = base + lane;
        if (ei < end) {
            int s = g_csr_src[ei];
            float4 el = *(const float4*)&g_el1[s * 4];
            sm_a[wid][lane * 4 + 0] = expf(lrelu(el.x + er.x) - m0) * i0;
            sm_a[wid][lane * 4 + 1] = expf(lrelu(el.y + er.y) - m1) * i1;
            sm_a[wid][lane * 4 + 2] = expf(lrelu(el.z + er.z) - m2) * i2;
            sm_a[wid][lane * 4 + 3] = expf(lrelu(el.w + er.w) - m3) * i3;
            sm_s[wid][lane] = s;
        }
        __syncwarp();
        int cnt = min(32, end - base);
        for (int j = 0; j < cnt; j++) {
            int s = sm_s[wid][j];
            float a = sm_a[wid][(j << 2) | hh];
            const float4* fp = (const float4*)&g_f1[(size_t)s * F1DIM + lane * 8];
            float4 u = fp[0], v = fp[1];
            acc0 += a * u.x; acc1 += a * u.y; acc2 += a * u.z; acc3 += a * u.w;
            acc4 += a * v.x; acc5 += a * v.y; acc6 += a * v.z; acc7 += a * v.w;
        }
        __syncwarp();
    }

    // write h1 = elu(acc + b1)
    const float* bp = b1 + lane * 8;
    float o[8] = {acc0 + bp[0], acc1 + bp[1], acc2 + bp[2], acc3 + bp[3],
                  acc4 + bp[4], acc5 + bp[5], acc6 + bp[6], acc7 + bp[7]};
#pragma unroll
    for (int c = 0; c < 8; c++) o[c] = o[c] > 0.f ? o[c] : expm1f(o[c]);
    float* hp = &g_h1[(size_t)d * F1DIM + lane * 8];
    *(float4*)hp       = make_float4(o[0], o[1], o[2], o[3]);
    *(float4*)(hp + 4) = make_float4(o[4], o[5], o[6], o[7]);
}

// --------------- layer-2 aggregation: warp per dst, 1 head -------------------
__global__ void agg2_kernel(const float* __restrict__ b2,
                            float* __restrict__ out) {
    __shared__ float sm_a[8][32];
    __shared__ int   sm_s[8][32];
    const int wid = threadIdx.x >> 5;
    const int lane = threadIdx.x & 31;
    const int d = blockIdx.x * 8 + wid;
    if (d >= N_NODES) return;
    const int start = g_cnt[d];
    const int end   = g_cnt[d + 1];

    float er = g_er2[d];
    float m = -INFINITY, q = 0.f;
    for (int base = start; base < end; base += 32) {
        int ei = base + lane;
        if (ei < end) {
            int s = g_csr_src[ei];
            onl_upd(m, q, lrelu(g_el2[s] + er));
        }
    }
#pragma unroll
    for (int off = 16; off > 0; off >>= 1) onl_comb(m, q, off);
    float iv = q > 0.f ? 1.0f / q : 0.f;

    float accx = 0.f, accy = 0.f;
    for (int base = start; base < end; base += 32) {
        int ei = base + lane;
        if (ei < end) {
            int s = g_csr_src[ei];
            sm_a[wid][lane] = expf(lrelu(g_el2[s] + er) - m) * iv;
            sm_s[wid][lane] = s;
        }
        __syncwarp();
        int cnt = min(32, end - base);
        for (int j = 0; j < cnt; j++) {
            int s = sm_s[wid][j];
            float a = sm_a[wid][j];
            float2 f = *(const float2*)&g_f2[(size_t)s * OUTD + lane * 2];
            accx += a * f.x;
            accy += a * f.y;
        }
        __syncwarp();
    }
    float2 o = make_float2(accx + b2[lane * 2], accy + b2[lane * 2 + 1]);
    *(float2*)&out[(size_t)d * OUTD + lane * 2] = o;
}

// ------------------------------ launch --------------------------------------
extern "C" void kernel_launch(void* const* d_in, const int* in_sizes, int n_in,
                              void* d_out, int out_size) {
    const float* features = (const float*)d_in[0];
    const float* W1  = (const float*)d_in[1];
    const float* al1 = (const float*)d_in[2];
    const float* ar1 = (const float*)d_in[3];
    const float* b1  = (const float*)d_in[4];
    const float* W2  = (const float*)d_in[5];
    const float* al2 = (const float*)d_in[6];
    const float* ar2 = (const float*)d_in[7];
    const float* b2  = (const float*)d_in[8];
    const int*   src = (const int*)d_in[9];
    const int*   dst = (const int*)d_in[10];
    float* out = (float*)d_out;

    float *p_f1, *p_h1, *p_f2;
    cudaGetSymbolAddress((void**)&p_f1, g_f1);
    cudaGetSymbolAddress((void**)&p_h1, g_h1);
    cudaGetSymbolAddress((void**)&p_f2, g_f2);

    // CSR build (shared by both layers)
    init_kernel<<<(N_NODES + 256) / 256, 256>>>();
    hist_kernel<<<(N_EDGES + 255) / 256, 256>>>(dst);
    scan_kernel<<<1, 1024>>>();
    fill_kernel<<<(N_EDGES + 255) / 256, 256>>>(src, dst);

    // Layer 1
    {
        dim3 grid(F1DIM / 64, (N_NODES + 127) / 128);
        sgemm_kernel<<<grid, 256>>>(features, W1, p_f1, N_NODES, F1DIM, IN_DIM);
    }
    elr1_kernel<<<(N_NODES * HEADS * 32 + 255) / 256, 256>>>(al1, ar1);
    agg1_kernel<<<(N_NODES + 7) / 8, 256>>>(b1);

    // Layer 2
    {
        dim3 grid(OUTD / 64, (N_NODES + 127) / 128);
        sgemm_kernel<<<grid, 256>>>(p_h1, W2, p_f2, N_NODES, OUTD, F1DIM);
    }
    elr2_kernel<<<(N_NODES * 32 + 255) / 256, 256>>>(al2, ar2);
    agg2_kernel<<<(N_NODES + 7) / 8, 256>>>(b2, out);
}

// round 6
// speedup vs baseline: 1.7295x; 1.2479x over previous
#include <cuda_runtime.h>
#include <cuda_bf16.h>
#include <cstdint>
#include <math.h>

// ---------------------------------------------------------------------------
// PubMedGAT round 5:
//  - mma.sync (bf16 HMMA) GEMMs, 3-term hi/lo split; B ldmatrix NON-trans fix
//  - CSR-by-dst edge phase (round-2 design)
// ---------------------------------------------------------------------------

#define N_NODES 50000
#define N_EDGES 800000
#define IN_DIM  512
#define HEADS   4
#define HID     64
#define F1DIM   (HEADS*HID)   // 256
#define OUTD    64
#define NEG_SLOPE 0.2f

// ------------------------- scratch (device globals) -------------------------
__device__ float          g_f1  [N_NODES * F1DIM];
__device__ __nv_bfloat16  g_a1hi[N_NODES * IN_DIM];
__device__ __nv_bfloat16  g_a1lo[N_NODES * IN_DIM];
__device__ __nv_bfloat16  g_h1hi[N_NODES * F1DIM];
__device__ __nv_bfloat16  g_h1lo[N_NODES * F1DIM];
__device__ float          g_f2  [N_NODES * OUTD];
__device__ float          g_el1 [N_NODES * HEADS];
__device__ float          g_er1 [N_NODES * HEADS];
__device__ float          g_el2 [N_NODES];
__device__ float          g_er2 [N_NODES];
__device__ int            g_cnt [N_NODES + 1];
__device__ int            g_cursor[N_NODES];
__device__ int            g_csr_src[N_EDGES];
__device__ __nv_bfloat16  g_w1hi[F1DIM * IN_DIM];   // [256 n-rows, 512 k]
__device__ __nv_bfloat16  g_w1lo[F1DIM * IN_DIM];
__device__ __nv_bfloat16  g_w2hi[OUTD * F1DIM];     // [64 n-rows, 256 k]
__device__ __nv_bfloat16  g_w2lo[OUTD * F1DIM];

// ------------------------------ helpers -------------------------------------
__device__ __forceinline__ uint32_t smem_to_u32(const void* p) {
    uint32_t a;
    asm("{ .reg .u64 t; cvta.to.shared.u64 t, %1; cvt.u32.u64 %0, t; }"
        : "=r"(a) : "l"(p));
    return a;
}
__device__ __forceinline__ void ldm_x4(unsigned* r, uint32_t addr) {
    asm volatile("ldmatrix.sync.aligned.m8n8.x4.shared.b16 {%0,%1,%2,%3}, [%4];"
                 : "=r"(r[0]), "=r"(r[1]), "=r"(r[2]), "=r"(r[3]) : "r"(addr));
}
__device__ __forceinline__ void mma16816(float* c, const unsigned* a,
                                         const unsigned* b) {
    asm volatile(
        "mma.sync.aligned.m16n8k16.row.col.f32.bf16.bf16.f32 "
        "{%0,%1,%2,%3}, {%4,%5,%6,%7}, {%8,%9}, {%0,%1,%2,%3};"
        : "+f"(c[0]), "+f"(c[1]), "+f"(c[2]), "+f"(c[3])
        : "r"(a[0]), "r"(a[1]), "r"(a[2]), "r"(a[3]), "r"(b[0]), "r"(b[1]));
}
__device__ __forceinline__ unsigned pk2(__nv_bfloat16 a, __nv_bfloat16 b) {
    unsigned short ua = __bfloat16_as_ushort(a);
    unsigned short ub = __bfloat16_as_ushort(b);
    return (unsigned)ua | ((unsigned)ub << 16);
}
__device__ __forceinline__ float lrelu(float x) {
    return x >= 0.0f ? x : NEG_SLOPE * x;
}
__device__ __forceinline__ void onl_upd(float& m, float& q, float e) {
    float nm = fmaxf(m, e);
    q = (m >= nm ? q : q * expf(m - nm)) + expf(e - nm);
    m = nm;
}
__device__ __forceinline__ void onl_comb(float& m, float& q, int off) {
    float mo = __shfl_xor_sync(0xFFFFFFFFu, m, off);
    float qo = __shfl_xor_sync(0xFFFFFFFFu, q, off);
    float nm = fmaxf(m, mo);
    float t1 = (m  >= nm) ? q  : q  * expf(m  - nm);
    float t2 = (mo >= nm) ? qo : qo * expf(mo - nm);
    m = nm; q = t1 + t2;
}

// ------------------------------ CSR build -----------------------------------
__global__ void init_kernel() {
    int i = blockIdx.x * blockDim.x + threadIdx.x;
    if (i <= N_NODES) g_cnt[i] = 0;
}
__global__ void hist_kernel(const int* __restrict__ dst) {
    int e = blockIdx.x * blockDim.x + threadIdx.x;
    if (e < N_EDGES) atomicAdd(&g_cnt[dst[e]], 1);
}
__global__ void scan_kernel() {
    __shared__ int sm[1024];
    const int t = threadIdx.x;
    const int CH = (N_NODES + 1023) / 1024;
    int lo = t * CH;
    int hi = min(N_NODES, lo + CH);
    int s = 0;
    for (int j = lo; j < hi; j++) s += g_cnt[j];
    sm[t] = s;
    __syncthreads();
    for (int off = 1; off < 1024; off <<= 1) {
        int u = (t >= off) ? sm[t - off] : 0;
        __syncthreads();
        if (t >= off) sm[t] += u;
        __syncthreads();
    }
    int run = (t > 0) ? sm[t - 1] : 0;
    for (int j = lo; j < hi; j++) {
        int c = g_cnt[j];
        g_cnt[j] = run;
        g_cursor[j] = run;
        run += c;
    }
    if (t == 1023) g_cnt[N_NODES] = run;
}
__global__ void fill_kernel(const int* __restrict__ src,
                            const int* __restrict__ dst) {
    int e = blockIdx.x * blockDim.x + threadIdx.x;
    if (e >= N_EDGES) return;
    int d = dst[e];
    int pos = atomicAdd(&g_cursor[d], 1);
    g_csr_src[pos] = src[e];
}

// ------------------------- split kernels -------------------------------------
__global__ void asplit_kernel(const float* __restrict__ A,
                              __nv_bfloat16* __restrict__ hi,
                              __nv_bfloat16* __restrict__ lo,
                              int total4) {
    int i = blockIdx.x * blockDim.x + threadIdx.x;
    if (i >= total4) return;
    float4 v = ((const float4*)A)[i];
    __nv_bfloat16 hx = __float2bfloat16(v.x), hy = __float2bfloat16(v.y);
    __nv_bfloat16 hz = __float2bfloat16(v.z), hw = __float2bfloat16(v.w);
    ((uint2*)hi)[i] = make_uint2(pk2(hx, hy), pk2(hz, hw));
    ((uint2*)lo)[i] = make_uint2(
        pk2(__float2bfloat16(v.x - __bfloat162float(hx)),
            __float2bfloat16(v.y - __bfloat162float(hy))),
        pk2(__float2bfloat16(v.z - __bfloat162float(hz)),
            __float2bfloat16(v.w - __bfloat162float(hw))));
}

// W [K rows, N cols] fp32 row-major -> hi/lo [N rows, K cols] bf16
__global__ void wsplit_kernel(const float* __restrict__ W,
                              __nv_bfloat16* __restrict__ hi,
                              __nv_bfloat16* __restrict__ lo,
                              int K, int N) {
    int i = blockIdx.x * blockDim.x + threadIdx.x;
    if (i >= K * N) return;
    int k = i / N, n = i % N;
    float v = W[i];
    __nv_bfloat16 h = __float2bfloat16(v);
    hi[(size_t)n * K + k] = h;
    lo[(size_t)n * K + k] = __float2bfloat16(v - __bfloat162float(h));
}

// --------------------- mma.sync split-bf16 GEMM ------------------------------
// C[M, NTOT] = A @ B^T; A hi/lo [M,KTOT] bf16, B hi/lo [NTOT rows, KTOT] bf16
// (B storage is col-major KxN => ldmatrix NON-trans for the B fragments).
// BM=128, BN per template, BK=64; 256 threads, 8 warps (4 M x 2 N).
template<int BN, int KTOT>
__global__ void __launch_bounds__(256)
gemm_mma(const __nv_bfloat16* __restrict__ Ahi,
         const __nv_bfloat16* __restrict__ Alo,
         const __nv_bfloat16* __restrict__ Bhi,
         const __nv_bfloat16* __restrict__ Blo,
         float* __restrict__ C, int M, int NTOT) {
    constexpr int WN = BN / 2;        // warp N extent
    constexpr int NA = WN / 8;        // n-atoms per warp
    constexpr int ROWB = 144;         // padded row bytes (72 bf16)
    constexpr int AH = 0;
    constexpr int AL = 128 * ROWB;
    constexpr int BH = 2 * 128 * ROWB;
    constexpr int BL = BH + BN * ROWB;

    extern __shared__ char smem[];
    const uint32_t sb = smem_to_u32(smem);
    const int tid = threadIdx.x;
    const int wid = tid >> 5, lane = tid & 31;
    const int wr = wid >> 1, wc = wid & 1;
    const int bm = blockIdx.x * 128;
    const int bn = blockIdx.y * BN;

    float acc[2][NA][4];
#pragma unroll
    for (int i = 0; i < 2; i++)
#pragma unroll
        for (int j = 0; j < NA; j++)
#pragma unroll
            for (int k = 0; k < 4; k++) acc[i][j][k] = 0.f;

    // ldmatrix lane address components (identical scheme for A and B)
    const int a_row = ((lane >> 3) & 1) * 8 + (lane & 7);   // + m0 + i*16
    const int a_col = (lane >> 4) * 8;                      // + kk*16
    const int b_row = ((lane >> 4) & 1) * 8 + (lane & 7);   // + n0 + p*16
    const int b_col = ((lane >> 3) & 1) * 8;                // + kk*16

    for (int kc = 0; kc < KTOT / 64; kc++) {
        // ---- load A tile [128 x 64] hi/lo
#pragma unroll
        for (int i = 0; i < 4; i++) {
            int idx = tid + i * 256;          // 0..1023
            int r = idx >> 3, c = idx & 7;
            int grow = bm + r;
            uint4 vh = make_uint4(0, 0, 0, 0), vl = make_uint4(0, 0, 0, 0);
            if (grow < M) {
                size_t g = (size_t)grow * KTOT + kc * 64 + c * 8;
                vh = *(const uint4*)&Ahi[g];
                vl = *(const uint4*)&Alo[g];
            }
            *(uint4*)(smem + AH + r * ROWB + c * 16) = vh;
            *(uint4*)(smem + AL + r * ROWB + c * 16) = vl;
        }
        // ---- load B tile [BN x 64] hi/lo
#pragma unroll
        for (int i = 0; i < BN / 32; i++) {
            int idx = tid + i * 256;
            int r = idx >> 3, c = idx & 7;
            size_t g = (size_t)(bn + r) * KTOT + kc * 64 + c * 8;
            *(uint4*)(smem + BH + r * ROWB + c * 16) = *(const uint4*)&Bhi[g];
            *(uint4*)(smem + BL + r * ROWB + c * 16) = *(const uint4*)&Blo[g];
        }
        __syncthreads();

#pragma unroll
        for (int kk = 0; kk < 4; kk++) {
            unsigned ah[2][4], al[2][4], bh[NA][2], bl[NA][2];
#pragma unroll
            for (int i = 0; i < 2; i++) {
                uint32_t ad = sb + (wr * 32 + i * 16 + a_row) * ROWB
                            + (kk * 16 + a_col) * 2;
                ldm_x4(ah[i], ad + AH);
                ldm_x4(al[i], ad + AL);
            }
#pragma unroll
            for (int p = 0; p < NA / 2; p++) {
                uint32_t bd = sb + (wc * WN + p * 16 + b_row) * ROWB
                            + (kk * 16 + b_col) * 2;
                unsigned t[4];
                ldm_x4(t, bd + BH);                 // NON-trans (B is [n][k])
                bh[2 * p][0] = t[0]; bh[2 * p][1] = t[1];
                bh[2 * p + 1][0] = t[2]; bh[2 * p + 1][1] = t[3];
                ldm_x4(t, bd + BL);
                bl[2 * p][0] = t[0]; bl[2 * p][1] = t[1];
                bl[2 * p + 1][0] = t[2]; bl[2 * p + 1][1] = t[3];
            }
#pragma unroll
            for (int i = 0; i < 2; i++)
#pragma unroll
                for (int j = 0; j < NA; j++) {
                    mma16816(acc[i][j], ah[i], bh[j]);
                    mma16816(acc[i][j], al[i], bh[j]);
                    mma16816(acc[i][j], ah[i], bl[j]);
                }
        }
        __syncthreads();
    }

    // ---- epilogue
#pragma unroll
    for (int i = 0; i < 2; i++) {
        int row = bm + wr * 32 + i * 16 + (lane >> 2);
#pragma unroll
        for (int j = 0; j < NA; j++) {
            int col = bn + wc * WN + j * 8 + (lane & 3) * 2;
            if (row < M)
                *(float2*)&C[(size_t)row * NTOT + col] =
                    make_float2(acc[i][j][0], acc[i][j][1]);
            if (row + 8 < M)
                *(float2*)&C[(size_t)(row + 8) * NTOT + col] =
                    make_float2(acc[i][j][2], acc[i][j][3]);
        }
    }
}

// --------------------- el/er projections (warp per node-head) ----------------
__global__ void elr1_kernel(const float* __restrict__ al,
                            const float* __restrict__ ar) {
    int w = (blockIdx.x * blockDim.x + threadIdx.x) >> 5;
    int lane = threadIdx.x & 31;
    if (w >= N_NODES * HEADS) return;
    int n = w >> 2, h = w & 3;
    const float* frow = g_f1 + (size_t)n * F1DIM + h * HID;
    float sl = 0.f, sr = 0.f;
#pragma unroll
    for (int i = lane; i < HID; i += 32) {
        float f = frow[i];
        sl += f * al[h * HID + i];
        sr += f * ar[h * HID + i];
    }
#pragma unroll
    for (int o = 16; o > 0; o >>= 1) {
        sl += __shfl_xor_sync(0xFFFFFFFFu, sl, o);
        sr += __shfl_xor_sync(0xFFFFFFFFu, sr, o);
    }
    if (lane == 0) { g_el1[n * 4 + h] = sl; g_er1[n * 4 + h] = sr; }
}

__global__ void elr2_kernel(const float* __restrict__ al,
                            const float* __restrict__ ar) {
    int w = (blockIdx.x * blockDim.x + threadIdx.x) >> 5;
    int lane = threadIdx.x & 31;
    if (w >= N_NODES) return;
    const float* frow = g_f2 + (size_t)w * OUTD;
    float sl = 0.f, sr = 0.f;
#pragma unroll
    for (int i = lane; i < OUTD; i += 32) {
        float f = frow[i];
        sl += f * al[i];
        sr += f * ar[i];
    }
#pragma unroll
    for (int o = 16; o > 0; o >>= 1) {
        sl += __shfl_xor_sync(0xFFFFFFFFu, sl, o);
        sr += __shfl_xor_sync(0xFFFFFFFFu, sr, o);
    }
    if (lane == 0) { g_el2[w] = sl; g_er2[w] = sr; }
}

// --------------- layer-1 aggregation: warp per dst, 4 heads ------------------
__global__ void agg1_kernel(const float* __restrict__ b1) {
    __shared__ float sm_a[8][128];
    __shared__ int   sm_s[8][32];
    const int wid = threadIdx.x >> 5;
    const int lane = threadIdx.x & 31;
    const int d = blockIdx.x * 8 + wid;
    if (d >= N_NODES) return;
    const int start = g_cnt[d];
    const int end   = g_cnt[d + 1];

    float4 er = *(const float4*)&g_er1[d * 4];

    float m0 = -INFINITY, m1 = -INFINITY, m2 = -INFINITY, m3 = -INFINITY;
    float q0 = 0.f, q1 = 0.f, q2 = 0.f, q3 = 0.f;
    for (int base = start; base < end; base += 32) {
        int ei = base + lane;
        if (ei < end) {
            int s = g_csr_src[ei];
            float4 el = *(const float4*)&g_el1[s * 4];
            onl_upd(m0, q0, lrelu(el.x + er.x));
            onl_upd(m1, q1, lrelu(el.y + er.y));
            onl_upd(m2, q2, lrelu(el.z + er.z));
            onl_upd(m3, q3, lrelu(el.w + er.w));
        }
    }
#pragma unroll
    for (int off = 16; off > 0; off >>= 1) {
        onl_comb(m0, q0, off);
        onl_comb(m1, q1, off);
        onl_comb(m2, q2, off);
        onl_comb(m3, q3, off);
    }
    float i0 = q0 > 0.f ? 1.0f / q0 : 0.f;
    float i1 = q1 > 0.f ? 1.0f / q1 : 0.f;
    float i2 = q2 > 0.f ? 1.0f / q2 : 0.f;
    float i3 = q3 > 0.f ? 1.0f / q3 : 0.f;

    const int hh = lane >> 3;
    float acc0 = 0.f, acc1 = 0.f, acc2 = 0.f, acc3 = 0.f;
    float acc4 = 0.f, acc5 = 0.f, acc6 = 0.f, acc7 = 0.f;
    for (int base = start; base < end; base += 32) {
        int ei = base + lane;
        if (ei < end) {
            int s = g_csr_src[ei];
            float4 el = *(const float4*)&g_el1[s * 4];
            sm_a[wid][lane * 4 + 0] = expf(lrelu(el.x + er.x) - m0) * i0;
            sm_a[wid][lane * 4 + 1] = expf(lrelu(el.y + er.y) - m1) * i1;
            sm_a[wid][lane * 4 + 2] = expf(lrelu(el.z + er.z) - m2) * i2;
            sm_a[wid][lane * 4 + 3] = expf(lrelu(el.w + er.w) - m3) * i3;
            sm_s[wid][lane] = s;
        }
        __syncwarp();
        int cnt = min(32, end - base);
        for (int j = 0; j < cnt; j++) {
            int s = sm_s[wid][j];
            float a = sm_a[wid][(j << 2) | hh];
            const float4* fp = (const float4*)&g_f1[(size_t)s * F1DIM + lane * 8];
            float4 u = fp[0], v = fp[1];
            acc0 += a * u.x; acc1 += a * u.y; acc2 += a * u.z; acc3 += a * u.w;
            acc4 += a * v.x; acc5 += a * v.y; acc6 += a * v.z; acc7 += a * v.w;
        }
        __syncwarp();
    }

    const float* bp = b1 + lane * 8;
    float o[8] = {acc0 + bp[0], acc1 + bp[1], acc2 + bp[2], acc3 + bp[3],
                  acc4 + bp[4], acc5 + bp[5], acc6 + bp[6], acc7 + bp[7]};
#pragma unroll
    for (int c = 0; c < 8; c++) o[c] = o[c] > 0.f ? o[c] : expm1f(o[c]);

    unsigned hv[4], lv[4];
#pragma unroll
    for (int p = 0; p < 4; p++) {
        __nv_bfloat16 h0 = __float2bfloat16(o[2 * p]);
        __nv_bfloat16 h1b = __float2bfloat16(o[2 * p + 1]);
        hv[p] = pk2(h0, h1b);
        lv[p] = pk2(__float2bfloat16(o[2 * p]     - __bfloat162float(h0)),
                    __float2bfloat16(o[2 * p + 1] - __bfloat162float(h1b)));
    }
    size_t off = (size_t)d * F1DIM + lane * 8;
    *(uint4*)&g_h1hi[off] = make_uint4(hv[0], hv[1], hv[2], hv[3]);
    *(uint4*)&g_h1lo[off] = make_uint4(lv[0], lv[1], lv[2], lv[3]);
}

// --------------- layer-2 aggregation: warp per dst, 1 head -------------------
__global__ void agg2_kernel(const float* __restrict__ b2,
                            float* __restrict__ out) {
    __shared__ float sm_a[8][32];
    __shared__ int   sm_s[8][32];
    const int wid = threadIdx.x >> 5;
    const int lane = threadIdx.x & 31;
    const int d = blockIdx.x * 8 + wid;
    if (d >= N_NODES) return;
    const int start = g_cnt[d];
    const int end   = g_cnt[d + 1];

    float er = g_er2[d];
    float m = -INFINITY, q = 0.f;
    for (int base = start; base < end; base += 32) {
        int ei = base + lane;
        if (ei < end) {
            int s = g_csr_src[ei];
            onl_upd(m, q, lrelu(g_el2[s] + er));
        }
    }
#pragma unroll
    for (int off = 16; off > 0; off >>= 1) onl_comb(m, q, off);
    float iv = q > 0.f ? 1.0f / q : 0.f;

    float accx = 0.f, accy = 0.f;
    for (int base = start; base < end; base += 32) {
        int ei = base + lane;
        if (ei < end) {
            int s = g_csr_src[ei];
            sm_a[wid][lane] = expf(lrelu(g_el2[s] + er) - m) * iv;
            sm_s[wid][lane] = s;
        }
        __syncwarp();
        int cnt = min(32, end - base);
        for (int j = 0; j < cnt; j++) {
            int s = sm_s[wid][j];
            float a = sm_a[wid][j];
            float2 f = *(const float2*)&g_f2[(size_t)s * OUTD + lane * 2];
            accx += a * f.x;
            accy += a * f.y;
        }
        __syncwarp();
    }
    float2 o = make_float2(accx + b2[lane * 2], accy + b2[lane * 2 + 1]);
    *(float2*)&out[(size_t)d * OUTD + lane * 2] = o;
}

// ------------------------------ launch --------------------------------------
extern "C" void kernel_launch(void* const* d_in, const int* in_sizes, int n_in,
                              void* d_out, int out_size) {
    const float* features = (const float*)d_in[0];
    const float* W1  = (const float*)d_in[1];
    const float* al1 = (const float*)d_in[2];
    const float* ar1 = (const float*)d_in[3];
    const float* b1  = (const float*)d_in[4];
    const float* W2  = (const float*)d_in[5];
    const float* al2 = (const float*)d_in[6];
    const float* ar2 = (const float*)d_in[7];
    const float* b2  = (const float*)d_in[8];
    const int*   src = (const int*)d_in[9];
    const int*   dst = (const int*)d_in[10];
    float* out = (float*)d_out;

    float *p_f1, *p_f2;
    __nv_bfloat16 *p_a1hi, *p_a1lo, *p_h1hi, *p_h1lo;
    __nv_bfloat16 *p_w1hi, *p_w1lo, *p_w2hi, *p_w2lo;
    cudaGetSymbolAddress((void**)&p_f1,   g_f1);
    cudaGetSymbolAddress((void**)&p_f2,   g_f2);
    cudaGetSymbolAddress((void**)&p_a1hi, g_a1hi);
    cudaGetSymbolAddress((void**)&p_a1lo, g_a1lo);
    cudaGetSymbolAddress((void**)&p_h1hi, g_h1hi);
    cudaGetSymbolAddress((void**)&p_h1lo, g_h1lo);
    cudaGetSymbolAddress((void**)&p_w1hi, g_w1hi);
    cudaGetSymbolAddress((void**)&p_w1lo, g_w1lo);
    cudaGetSymbolAddress((void**)&p_w2hi, g_w2hi);
    cudaGetSymbolAddress((void**)&p_w2lo, g_w2lo);

    constexpr int SMEM1 = 2 * 128 * 144 + 2 * 128 * 144;  // 73728
    constexpr int SMEM2 = 2 * 128 * 144 + 2 * 64 * 144;   // 55296
    cudaFuncSetAttribute(gemm_mma<128, 512>,
                         cudaFuncAttributeMaxDynamicSharedMemorySize, SMEM1);
    cudaFuncSetAttribute(gemm_mma<64, 256>,
                         cudaFuncAttributeMaxDynamicSharedMemorySize, SMEM2);

    const int MTILES = (N_NODES + 127) / 128;  // 391

    // CSR build
    init_kernel<<<(N_NODES + 256) / 256, 256>>>();
    hist_kernel<<<(N_EDGES + 255) / 256, 256>>>(dst);
    scan_kernel<<<1, 1024>>>();
    fill_kernel<<<(N_EDGES + 255) / 256, 256>>>(src, dst);

    // splits
    asplit_kernel<<<(N_NODES * IN_DIM / 4 + 255) / 256, 256>>>(
        features, p_a1hi, p_a1lo, N_NODES * IN_DIM / 4);
    wsplit_kernel<<<(IN_DIM * F1DIM + 255) / 256, 256>>>(W1, p_w1hi, p_w1lo, IN_DIM, F1DIM);
    wsplit_kernel<<<(F1DIM * OUTD + 255) / 256, 256>>>(W2, p_w2hi, p_w2lo, F1DIM, OUTD);

    // Layer 1
    {
        dim3 grid(MTILES, F1DIM / 128);
        gemm_mma<128, 512><<<grid, 256, SMEM1>>>(
            p_a1hi, p_a1lo, p_w1hi, p_w1lo, p_f1, N_NODES, F1DIM);
    }
    elr1_kernel<<<(N_NODES * HEADS * 32 + 255) / 256, 256>>>(al1, ar1);
    agg1_kernel<<<(N_NODES + 7) / 8, 256>>>(b1);

    // Layer 2
    {
        dim3 grid(MTILES, 1);
        gemm_mma<64, 256><<<grid, 256, SMEM2>>>(
            p_h1hi, p_h1lo, p_w2hi, p_w2lo, p_f2, N_NODES, OUTD);
    }
    elr2_kernel<<<(N_NODES * 32 + 255) / 256, 256>>>(al2, ar2);
    agg2_kernel<<<(N_NODES + 7) / 8, 256>>>(b2, out);
}